// round 4
// baseline (speedup 1.0000x reference)
#include <cuda_runtime.h>

// Problem dims (fixed)
#define BB_  64
#define TT_  1024
#define DD_  512
#define HH_  512

// Scratch: xp[dir][b][s][h] (backward stored already time-reversed)
__device__ float g_xp[(size_t)2 * BB_ * TT_ * HH_];

// ---------------------------------------------------------------------------
// Kernel 1: input projection GEMM (fp32 SIMT, 128x128x16 tiles, 8x8 microtile)
// xp[dir][b][s][n] = sum_d x[b,t,d] * Wih_dir[n,d] + bih_dir[n] + bhh_dir[n]
// dir==0: s = t ; dir==1: s = T-1-t (reversed at write time)
// ---------------------------------------------------------------------------
__global__ void __launch_bounds__(256) proj_kernel(
    const float* __restrict__ x,
    const float* __restrict__ Wih_f, const float* __restrict__ Wih_b,
    const float* __restrict__ bih_f, const float* __restrict__ bhh_f,
    const float* __restrict__ bih_b, const float* __restrict__ bhh_b)
{
    __shared__ float As[16][128];   // As[k][m]
    __shared__ float Bs[16][128];   // Bs[k][n]

    const int dir = blockIdx.z;
    const float* __restrict__ W  = dir ? Wih_b : Wih_f;
    const float* __restrict__ bi = dir ? bih_b : bih_f;
    const float* __restrict__ bh = dir ? bhh_b : bhh_f;

    const int m0 = blockIdx.x * 128;   // row block within B*T = 65536
    const int n0 = blockIdx.y * 128;   // col block within H = 512
    const int tid = threadIdx.x;
    const int tr = tid >> 4;           // 0..15
    const int tc = tid & 15;           // 0..15

    float acc[8][8];
    #pragma unroll
    for (int i = 0; i < 8; i++)
        #pragma unroll
        for (int j = 0; j < 8; j++) acc[i][j] = 0.0f;

    for (int k0 = 0; k0 < 512; k0 += 16) {
        #pragma unroll
        for (int p = 0; p < 2; p++) {
            int idx = tid + p * 256;       // float4 index 0..511 in 128x16 tile
            int row = idx >> 2;            // 0..127
            int kc  = (idx & 3) * 4;       // 0,4,8,12
            float4 va = *(const float4*)(x + (size_t)(m0 + row) * 512 + k0 + kc);
            As[kc + 0][row] = va.x; As[kc + 1][row] = va.y;
            As[kc + 2][row] = va.z; As[kc + 3][row] = va.w;
            float4 vb = *(const float4*)(W + (size_t)(n0 + row) * 512 + k0 + kc);
            Bs[kc + 0][row] = vb.x; Bs[kc + 1][row] = vb.y;
            Bs[kc + 2][row] = vb.z; Bs[kc + 3][row] = vb.w;
        }
        __syncthreads();

        #pragma unroll
        for (int kk = 0; kk < 16; kk++) {
            float av[8], bv[8];
            float4 t0 = *(const float4*)&As[kk][tr * 8];
            float4 t1 = *(const float4*)&As[kk][tr * 8 + 4];
            av[0] = t0.x; av[1] = t0.y; av[2] = t0.z; av[3] = t0.w;
            av[4] = t1.x; av[5] = t1.y; av[6] = t1.z; av[7] = t1.w;
            float4 u0 = *(const float4*)&Bs[kk][tc * 8];
            float4 u1 = *(const float4*)&Bs[kk][tc * 8 + 4];
            bv[0] = u0.x; bv[1] = u0.y; bv[2] = u0.z; bv[3] = u0.w;
            bv[4] = u1.x; bv[5] = u1.y; bv[6] = u1.z; bv[7] = u1.w;
            #pragma unroll
            for (int i = 0; i < 8; i++)
                #pragma unroll
                for (int j = 0; j < 8; j++)
                    acc[i][j] += av[i] * bv[j];
        }
        __syncthreads();
    }

    float bias[8];
    #pragma unroll
    for (int j = 0; j < 8; j++) {
        int n = n0 + tc * 8 + j;
        bias[j] = __ldg(bi + n) + __ldg(bh + n);
    }

    #pragma unroll
    for (int i = 0; i < 8; i++) {
        int m = m0 + tr * 8 + i;
        int b = m >> 10;
        int t = m & 1023;
        int s = dir ? (1023 - t) : t;
        float* op = g_xp + (((size_t)dir * 64 + b) * 1024 + (size_t)s) * 512 + n0 + tc * 8;
        float4 o0 = make_float4(acc[i][0] + bias[0], acc[i][1] + bias[1],
                                acc[i][2] + bias[2], acc[i][3] + bias[3]);
        float4 o1 = make_float4(acc[i][4] + bias[4], acc[i][5] + bias[5],
                                acc[i][6] + bias[6], acc[i][7] + bias[7]);
        *(float4*)(op)     = o0;
        *(float4*)(op + 4) = o1;
    }
}

// ---------------------------------------------------------------------------
// Kernel 2: persistent recurrence. One kernel, 1024 steps internally.
// 16 clusters of 8 CTAs (128 CTAs, one wave). Cluster = (dir, 8 batches).
// Each CTA owns 64 Whh rows, register-resident (128 floats/thread).
// h passes step-to-step through `out` (gmem/L2); cluster barrier per step.
// ---------------------------------------------------------------------------
__device__ __forceinline__ float fast_tanh(float v) {
    float a = fabsf(v);
    float e = __expf(-2.0f * a);
    float r = __fdividef(1.0f - e, 1.0f + e);
    return copysignf(r, v);
}

__global__ void __launch_bounds__(256, 1) __cluster_dims__(8, 1, 1)
scan_kernel(const float* __restrict__ Whh_f, const float* __restrict__ Whh_b,
            float* __restrict__ out)
{
    __shared__ float hs[8][512];   // h_prev for the cluster's 8 batches

    const int cta     = blockIdx.x;      // 0..127
    const int cluster = cta >> 3;        // 0..15
    const int rank    = cta & 7;         // CTA rank in cluster -> j slice
    const int dir     = cluster >> 3;    // 0..1
    const int b0      = (cluster & 7) * 8;
    const int tid  = threadIdx.x;
    const int w    = tid >> 5;           // warp 0..7 -> 8 j rows each
    const int lane = tid & 31;
    const int jq   = lane & 3;           // j sub-row
    const int kq   = lane >> 2;          // k group 0..7
    const int j0   = rank * 64 + w * 8 + jq;   // global j, row 0
    const int j1   = j0 + 4;                   // global j, row 1

    const float* __restrict__ Whh = dir ? Whh_b : Whh_f;

    // Register-resident weights, interleaved k layout (bank-conflict-free):
    // lane kq covers k = i*32 + kq*4 + {0..3}, i = 0..15  (union over kq = all 512)
    float4 wv0[16], wv1[16];
    #pragma unroll
    for (int i = 0; i < 16; i++) {
        wv0[i] = *(const float4*)(Whh + (size_t)j0 * 512 + i * 32 + kq * 4);
        wv1[i] = *(const float4*)(Whh + (size_t)j1 * 512 + i * 32 + kq * 4);
    }

    #pragma unroll 1
    for (int s = 0; s < 1024; s++) {
        // Stage h_prev into SMEM (zeros at s==0). 1024 float4, 4 per thread.
        if (s == 0) {
            #pragma unroll
            for (int p = 0; p < 4; p++)
                ((float4*)hs)[tid + p * 256] = make_float4(0.f, 0.f, 0.f, 0.f);
        } else {
            #pragma unroll
            for (int p = 0; p < 4; p++) {
                int f = tid + p * 256;       // b*128 + off4
                int b = f >> 7;
                int off4 = f & 127;
                ((float4*)hs)[f] = *(const float4*)(out +
                    (((size_t)((b0 + b) * 2 + dir)) * 1024 + (s - 1)) * 512 + off4 * 4);
            }
        }
        __syncthreads();

        // xp prefetch for writer lanes (kq==0)
        float xq0[8], xq1[8];
        if (kq == 0) {
            #pragma unroll
            for (int b = 0; b < 8; b++) {
                const float* xpb = g_xp + (((size_t)dir * 64 + b0 + b) * 1024 + s) * 512;
                xq0[b] = __ldg(xpb + j0);
                xq1[b] = __ldg(xpb + j1);
            }
        }

        float acc0[8], acc1[8];
        #pragma unroll
        for (int b = 0; b < 8; b++) { acc0[b] = 0.f; acc1[b] = 0.f; }

        #pragma unroll
        for (int i = 0; i < 16; i++) {
            const float4 w0 = wv0[i];
            const float4 w1 = wv1[i];
            #pragma unroll
            for (int b = 0; b < 8; b++) {
                const float4 h4 = *(const float4*)&hs[b][i * 32 + kq * 4];
                acc0[b] = fmaf(w0.x, h4.x, acc0[b]);
                acc0[b] = fmaf(w0.y, h4.y, acc0[b]);
                acc0[b] = fmaf(w0.z, h4.z, acc0[b]);
                acc0[b] = fmaf(w0.w, h4.w, acc0[b]);
                acc1[b] = fmaf(w1.x, h4.x, acc1[b]);
                acc1[b] = fmaf(w1.y, h4.y, acc1[b]);
                acc1[b] = fmaf(w1.z, h4.z, acc1[b]);
                acc1[b] = fmaf(w1.w, h4.w, acc1[b]);
            }
        }

        // Reduce over the 8 kq lanes (lane bits 2,3,4 -> xor 4, 8, 16)
        #pragma unroll
        for (int b = 0; b < 8; b++) {
            #pragma unroll
            for (int m = 4; m <= 16; m <<= 1) {
                acc0[b] += __shfl_xor_sync(0xFFFFFFFFu, acc0[b], m);
                acc1[b] += __shfl_xor_sync(0xFFFFFFFFu, acc1[b], m);
            }
        }

        if (kq == 0) {
            #pragma unroll
            for (int b = 0; b < 8; b++) {
                float* ob = out + (((size_t)((b0 + b) * 2 + dir)) * 1024 + s) * 512;
                ob[j0] = fast_tanh(acc0[b] + xq0[b]);
                ob[j1] = fast_tanh(acc1[b] + xq1[b]);
            }
        }

        // Cluster-wide barrier: release makes our out[s] writes visible to
        // peers; acquire on wait lets us read their out[s] next iteration.
        // Also acts as a full CTA barrier protecting hs reuse.
        asm volatile("barrier.cluster.arrive.aligned;" ::: "memory");
        asm volatile("barrier.cluster.wait.aligned;"   ::: "memory");
    }
}

// ---------------------------------------------------------------------------
extern "C" void kernel_launch(void* const* d_in, const int* in_sizes, int n_in,
                              void* d_out, int out_size)
{
    (void)in_sizes; (void)n_in; (void)out_size;
    const float* x     = (const float*)d_in[0];
    const float* Wih_f = (const float*)d_in[1];
    const float* Whh_f = (const float*)d_in[2];
    const float* bih_f = (const float*)d_in[3];
    const float* bhh_f = (const float*)d_in[4];
    const float* Wih_b = (const float*)d_in[5];
    const float* Whh_b = (const float*)d_in[6];
    const float* bih_b = (const float*)d_in[7];
    const float* bhh_b = (const float*)d_in[8];
    float* out = (float*)d_out;

    // Input projections for both directions (backward stored time-reversed)
    proj_kernel<<<dim3(512, 4, 2), 256>>>(x, Wih_f, Wih_b, bih_f, bhh_f, bih_b, bhh_b);

    // Persistent recurrence: 16 clusters x 8 CTAs, 1024 steps internally.
    scan_kernel<<<128, 256>>>(Whh_f, Whh_b, out);
}

// round 11
// speedup vs baseline: 1.2295x; 1.2295x over previous
#include <cuda_runtime.h>
#include <cstdint>

// Problem dims (fixed)
#define BB_  64
#define TT_  1024
#define DD_  512
#define HH_  512

// Scratch: xp[dir][b][s][h] (backward stored already time-reversed)
__device__ float g_xp[(size_t)2 * BB_ * TT_ * HH_];

// ---------------------------------------------------------------------------
// Kernel 1: input projection GEMM (fp32 SIMT, 128x128x16 tiles, 8x8 microtile)
// xp[dir][b][s][n] = sum_d x[b,t,d] * Wih_dir[n,d] + bih_dir[n] + bhh_dir[n]
// dir==0: s = t ; dir==1: s = T-1-t (reversed at write time)
// ---------------------------------------------------------------------------
__global__ void __launch_bounds__(256) proj_kernel(
    const float* __restrict__ x,
    const float* __restrict__ Wih_f, const float* __restrict__ Wih_b,
    const float* __restrict__ bih_f, const float* __restrict__ bhh_f,
    const float* __restrict__ bih_b, const float* __restrict__ bhh_b)
{
    __shared__ float As[16][128];   // As[k][m]
    __shared__ float Bs[16][128];   // Bs[k][n]

    const int dir = blockIdx.z;
    const float* __restrict__ W  = dir ? Wih_b : Wih_f;
    const float* __restrict__ bi = dir ? bih_b : bih_f;
    const float* __restrict__ bh = dir ? bhh_b : bhh_f;

    const int m0 = blockIdx.x * 128;   // row block within B*T = 65536
    const int n0 = blockIdx.y * 128;   // col block within H = 512
    const int tid = threadIdx.x;
    const int tr = tid >> 4;           // 0..15
    const int tc = tid & 15;           // 0..15

    float acc[8][8];
    #pragma unroll
    for (int i = 0; i < 8; i++)
        #pragma unroll
        for (int j = 0; j < 8; j++) acc[i][j] = 0.0f;

    for (int k0 = 0; k0 < 512; k0 += 16) {
        #pragma unroll
        for (int p = 0; p < 2; p++) {
            int idx = tid + p * 256;       // float4 index 0..511 in 128x16 tile
            int row = idx >> 2;            // 0..127
            int kc  = (idx & 3) * 4;       // 0,4,8,12
            float4 va = *(const float4*)(x + (size_t)(m0 + row) * 512 + k0 + kc);
            As[kc + 0][row] = va.x; As[kc + 1][row] = va.y;
            As[kc + 2][row] = va.z; As[kc + 3][row] = va.w;
            float4 vb = *(const float4*)(W + (size_t)(n0 + row) * 512 + k0 + kc);
            Bs[kc + 0][row] = vb.x; Bs[kc + 1][row] = vb.y;
            Bs[kc + 2][row] = vb.z; Bs[kc + 3][row] = vb.w;
        }
        __syncthreads();

        #pragma unroll
        for (int kk = 0; kk < 16; kk++) {
            float av[8], bv[8];
            float4 t0 = *(const float4*)&As[kk][tr * 8];
            float4 t1 = *(const float4*)&As[kk][tr * 8 + 4];
            av[0] = t0.x; av[1] = t0.y; av[2] = t0.z; av[3] = t0.w;
            av[4] = t1.x; av[5] = t1.y; av[6] = t1.z; av[7] = t1.w;
            float4 u0 = *(const float4*)&Bs[kk][tc * 8];
            float4 u1 = *(const float4*)&Bs[kk][tc * 8 + 4];
            bv[0] = u0.x; bv[1] = u0.y; bv[2] = u0.z; bv[3] = u0.w;
            bv[4] = u1.x; bv[5] = u1.y; bv[6] = u1.z; bv[7] = u1.w;
            #pragma unroll
            for (int i = 0; i < 8; i++)
                #pragma unroll
                for (int j = 0; j < 8; j++)
                    acc[i][j] += av[i] * bv[j];
        }
        __syncthreads();
    }

    float bias[8];
    #pragma unroll
    for (int j = 0; j < 8; j++) {
        int n = n0 + tc * 8 + j;
        bias[j] = __ldg(bi + n) + __ldg(bh + n);
    }

    #pragma unroll
    for (int i = 0; i < 8; i++) {
        int m = m0 + tr * 8 + i;
        int b = m >> 10;
        int t = m & 1023;
        int s = dir ? (1023 - t) : t;
        float* op = g_xp + (((size_t)dir * 64 + b) * 1024 + (size_t)s) * 512 + n0 + tc * 8;
        float4 o0 = make_float4(acc[i][0] + bias[0], acc[i][1] + bias[1],
                                acc[i][2] + bias[2], acc[i][3] + bias[3]);
        float4 o1 = make_float4(acc[i][4] + bias[4], acc[i][5] + bias[5],
                                acc[i][6] + bias[6], acc[i][7] + bias[7]);
        *(float4*)(op)     = o0;
        *(float4*)(op + 4) = o1;
    }
}

// ---------------------------------------------------------------------------
// Kernel 2: persistent recurrence, DSMEM st.async h-exchange.
// 16 clusters of 8 CTAs (128 CTAs). Cluster = (dir, 8 batches).
// Each CTA owns 64 Whh rows register-resident (J=4 rows x KQ=16 k-split).
// h passes step-to-step via st.async into all peers' SMEM; mbarrier
// (tx-counted, double-buffered) replaces barrier.cluster + gmem round-trip.
// ---------------------------------------------------------------------------
__device__ __forceinline__ float fast_tanh(float v) {
    float a = fabsf(v);
    float e = __expf(-2.0f * a);
    float r = __fdividef(1.0f - e, 1.0f + e);
    return copysignf(r, v);
}

__device__ __forceinline__ uint32_t smem_u32(const void* p) {
    uint32_t a;
    asm("{ .reg .u64 t; cvta.to.shared.u64 t, %1; cvt.u32.u64 %0, t; }"
        : "=r"(a) : "l"(p));
    return a;
}

__device__ __forceinline__ void mbar_init(uint32_t addr, uint32_t cnt) {
    asm volatile("mbarrier.init.shared.b64 [%0], %1;" :: "r"(addr), "r"(cnt) : "memory");
}
__device__ __forceinline__ void mbar_inval(uint32_t addr) {
    asm volatile("mbarrier.inval.shared.b64 [%0];" :: "r"(addr) : "memory");
}
__device__ __forceinline__ void mbar_arrive_expect_tx(uint32_t addr, uint32_t bytes) {
    asm volatile("mbarrier.arrive.expect_tx.shared.b64 _, [%0], %1;"
                 :: "r"(addr), "r"(bytes) : "memory");
}
__device__ __forceinline__ void mbar_wait_parity(uint32_t addr, uint32_t parity) {
    asm volatile(
        "{\n\t"
        ".reg .pred P;\n"
        "WL%=:\n\t"
        "mbarrier.try_wait.parity.shared.b64 P, [%0], %1, 0x989680;\n\t"
        "@!P bra WL%=;\n\t"
        "}"
        :: "r"(addr), "r"(parity) : "memory");
}
__device__ __forceinline__ void st_async_v2(uint32_t raddr, uint32_t u0, uint32_t u1,
                                            uint32_t rmbar) {
    asm volatile(
        "st.async.shared::cluster.mbarrier::complete_tx::bytes.v2.b32 [%0], {%1, %2}, [%3];"
        :: "r"(raddr), "r"(u0), "r"(u1), "r"(rmbar) : "memory");
}
__device__ __forceinline__ uint32_t mapa_u32(uint32_t laddr, uint32_t rank) {
    uint32_t r;
    asm("mapa.shared::cluster.u32 %0, %1, %2;" : "=r"(r) : "r"(laddr), "r"(rank));
    return r;
}

#define HS_BUF_BYTES 16384u   // 8 batches * 512 floats * 4B

__global__ void __launch_bounds__(256, 1) __cluster_dims__(8, 1, 1)
scan_kernel(const float* __restrict__ Whh_f, const float* __restrict__ Whh_b,
            float* __restrict__ out)
{
    __shared__ float hs[2][8][512];                       // 32 KB, double-buffered h
    __shared__ __align__(16) unsigned long long mbar[2];  // one per buffer

    const int cta     = blockIdx.x;      // 0..127
    const int cluster = cta >> 3;        // 0..15
    const int rank    = cta & 7;         // CTA rank in cluster -> j slice
    const int dir     = cluster >> 3;    // 0..1
    const int b0      = (cluster & 7) * 8;
    const int tid  = threadIdx.x;
    const int w    = tid >> 5;           // warp 0..7
    const int lane = tid & 31;
    const int jt   = lane & 1;           // j sub-block (0/1)
    const int kq   = lane >> 1;          // k group 0..15
    const int jb   = rank * 64 + w * 8 + jt * 4;   // 4 consecutive rows jb..jb+3

    const float* __restrict__ Whh = dir ? Whh_b : Whh_f;

    // Register-resident weights: wv[r][i] covers k = i*64 + kq*4 + {0..3}
    float4 wv[4][8];
    #pragma unroll
    for (int r = 0; r < 4; r++)
        #pragma unroll
        for (int i = 0; i < 8; i++)
            wv[r][i] = *(const float4*)(Whh + (size_t)(jb + r) * 512 + i * 64 + kq * 4);

    // Final-value ownership after reduce-scatter:
    const int bmy = kq >> 1;                  // owned batch 0..7
    const int gb  = b0 + bmy;                 // global batch
    const int j0  = jb + 2 * (kq & 1);        // owned j pair: j0, j0+1

    const uint32_t hs_base   = smem_u32(&hs[0][0][0]);
    const uint32_t mbar_base = smem_u32(&mbar[0]);
    const uint32_t mb_rel    = mbar_base - hs_base;

    // Remote bases (one mapa per peer; all other remote addrs are offsets)
    uint32_t peer_base[8];
    #pragma unroll
    for (int p = 0; p < 8; p++) peer_base[p] = mapa_u32(hs_base, (uint32_t)p);

    // Init: mbarriers (count=1) + zero hs[1] (h(-1) = 0)
    if (tid == 0) { mbar_init(mbar_base, 1); mbar_init(mbar_base + 8, 1); }
    #pragma unroll
    for (int p = 0; p < 4; p++)
        ((float4*)&hs[1][0][0])[tid + p * 256] = make_float4(0.f, 0.f, 0.f, 0.f);
    __syncthreads();
    if (tid == 0) {
        mbar_arrive_expect_tx(mbar_base, HS_BUF_BYTES);       // arm buf0 for h(0)
        mbar_arrive_expect_tx(mbar_base + 8, HS_BUF_BYTES);   // arm buf1 for h(1)
    }
    // All CTAs armed + zeroed before any peer st.async arrives
    asm volatile("barrier.cluster.arrive.aligned;" ::: "memory");
    asm volatile("barrier.cluster.wait.aligned;"   ::: "memory");

    const float* xp_base = g_xp + (((size_t)dir * 64 + gb) * 1024) * 512 + j0;
    float* out_base = out + ((size_t)(gb * 2 + dir) * 1024) * 512 + j0;

    #pragma unroll 1
    for (int s = 0; s < 1024; s++) {
        const int bufR = (s - 1) & 1;        // read buffer (s=0 -> zeroed buf1)

        // xp prefetch (hidden behind wait + compute)
        const float2 xq = *(const float2*)(xp_base + (size_t)s * 512);

        if (s > 0) {
            mbar_wait_parity(mbar_base + bufR * 8, ((s - 1) >> 1) & 1);
            // Re-arm this buffer for h(s+1). Race-free: peers cannot produce
            // h(s+1) before consuming my h(s), which I send below.
            if (tid == 0 && s < 1022)
                mbar_arrive_expect_tx(mbar_base + bufR * 8, HS_BUF_BYTES);
        }

        // Main FMA block: acc[r][b] += sum_k Whh[jb+r][k] * h[b][k]
        const float* hb = &hs[bufR][0][0];
        float acc[4][8];
        #pragma unroll
        for (int r = 0; r < 4; r++)
            #pragma unroll
            for (int b = 0; b < 8; b++) acc[r][b] = 0.0f;

        #pragma unroll
        for (int i = 0; i < 8; i++) {
            #pragma unroll
            for (int b = 0; b < 8; b++) {
                const float4 h4 = *(const float4*)(hb + b * 512 + i * 64 + kq * 4);
                #pragma unroll
                for (int r = 0; r < 4; r++) {
                    acc[r][b] = fmaf(wv[r][i].x, h4.x, acc[r][b]);
                    acc[r][b] = fmaf(wv[r][i].y, h4.y, acc[r][b]);
                    acc[r][b] = fmaf(wv[r][i].z, h4.z, acc[r][b]);
                    acc[r][b] = fmaf(wv[r][i].w, h4.w, acc[r][b]);
                }
            }
        }

        // Reduce-scatter over the 16 kq lanes (30 shfl total).
        // Stage 1 (mask 2, kq bit0): keep my r-pair.
        float r1[16];
        {
            const int hi = (lane >> 1) & 1;
            #pragma unroll
            for (int t = 0; t < 16; t++) {
                int b = t & 7, rr = t >> 3;
                float keep = hi ? acc[2 + rr][b] : acc[rr][b];
                float send = hi ? acc[rr][b]     : acc[2 + rr][b];
                r1[t] = keep + __shfl_xor_sync(0xFFFFFFFFu, send, 2);
            }
        }
        // Stage 2 (mask 4, kq bit1): fix b bit0.
        float r2[8];
        {
            const int hi = (lane >> 2) & 1;
            #pragma unroll
            for (int t = 0; t < 8; t++) {
                int b23 = t & 3, rr = t >> 2;
                float keep = r1[rr * 8 + (b23 * 2 + hi)];
                float send = r1[rr * 8 + (b23 * 2 + (hi ^ 1))];
                r2[t] = keep + __shfl_xor_sync(0xFFFFFFFFu, send, 4);
            }
        }
        // Stage 3 (mask 8, kq bit2): fix b bit1.
        float r3[4];
        {
            const int hi = (lane >> 3) & 1;
            #pragma unroll
            for (int t = 0; t < 4; t++) {
                int b3 = t & 1, rr = t >> 1;
                float keep = r2[rr * 4 + (b3 * 2 + hi)];
                float send = r2[rr * 4 + (b3 * 2 + (hi ^ 1))];
                r3[t] = keep + __shfl_xor_sync(0xFFFFFFFFu, send, 8);
            }
        }
        // Stage 4 (mask 16, kq bit3): fix b bit2. Final 2 values (j0, j0+1).
        float f0, f1;
        {
            const int hi = (lane >> 4) & 1;
            f0 = r3[hi]     + __shfl_xor_sync(0xFFFFFFFFu, r3[hi ^ 1], 16);
            f1 = r3[2 + hi] + __shfl_xor_sync(0xFFFFFFFFu, r3[2 + (hi ^ 1)], 16);
        }

        const float v0 = fast_tanh(f0 + xq.x);
        const float v1 = fast_tanh(f1 + xq.y);

        // Output write (off critical path)
        *(float2*)(out_base + (size_t)s * 512) = make_float2(v0, v1);

        // Push h(s) to all 8 peers' hs[s&1] with tx-counted completion.
        if (s < 1023) {
            const uint32_t u0 = __float_as_uint(v0);
            const uint32_t u1 = __float_as_uint(v1);
            const uint32_t off = (uint32_t)(s & 1) * HS_BUF_BYTES
                               + (uint32_t)bmy * 2048u + (uint32_t)j0 * 4u;
            const uint32_t mboff = mb_rel + (uint32_t)(s & 1) * 8u;
            #pragma unroll
            for (int p = 0; p < 8; p++)
                st_async_v2(peer_base[p] + off, u0, u1, peer_base[p] + mboff);
        }
    }

    __syncthreads();
    if (tid == 0) { mbar_inval(mbar_base); mbar_inval(mbar_base + 8); }
}

// ---------------------------------------------------------------------------
extern "C" void kernel_launch(void* const* d_in, const int* in_sizes, int n_in,
                              void* d_out, int out_size)
{
    (void)in_sizes; (void)n_in; (void)out_size;
    const float* x     = (const float*)d_in[0];
    const float* Wih_f = (const float*)d_in[1];
    const float* Whh_f = (const float*)d_in[2];
    const float* bih_f = (const float*)d_in[3];
    const float* bhh_f = (const float*)d_in[4];
    const float* Wih_b = (const float*)d_in[5];
    const float* Whh_b = (const float*)d_in[6];
    const float* bih_b = (const float*)d_in[7];
    const float* bhh_b = (const float*)d_in[8];
    float* out = (float*)d_out;

    // Input projections for both directions (backward stored time-reversed)
    proj_kernel<<<dim3(512, 4, 2), 256>>>(x, Wih_f, Wih_b, bih_f, bhh_f, bih_b, bhh_b);

    // Persistent recurrence: 16 clusters x 8 CTAs, 1024 steps internally.
    scan_kernel<<<128, 256>>>(Whh_f, Whh_b, out);
}